// round 1
// baseline (speedup 1.0000x reference)
#include <cuda_runtime.h>
#include <math.h>
#include <stdint.h>
#include <float.h>

#define B_ 16
#define T_ 2048
#define D_ 512
#define H_ 64

// ---------------- device scratch (no allocations allowed) ----------------
__device__ float4 g_P[B_ * T_];          // 4-momenta, 512 KB
__device__ int    g_len[B_];             // valid lengths per batch
__device__ float  g_mass[B_ * T_ * 3];   // masses for k=2,4,8

// =========================================================================
// Kernel 1: compute P = (E, px, py, pz) and per-batch valid length.
// Handles mask stored as 1-byte bool OR 4-byte int/float (runtime detect).
// =========================================================================
__global__ __launch_bounds__(256) void prep_kernel(
    const float* __restrict__ tokens, const unsigned char* __restrict__ mask)
{
    int b = blockIdx.x;
    unsigned int w0 = *(const unsigned int*)mask;   // first 4 bytes of mask
    bool byteMode = (w0 == 0x01010101u);            // 1-byte-per-element layout

    int cnt = 0;
    for (int s = threadIdx.x; s < T_; s += blockDim.x) {
        int gt = b * T_ + s;
        unsigned int mv;
        if (byteMode) mv = (unsigned int)mask[gt];
        else          mv = ((const unsigned int*)mask)[gt];  // int32 or float32 bits
        cnt += (mv != 0u);

        float E   = tokens[gt * 4 + 0];
        float Pt  = tokens[gt * 4 + 1];
        float eta = tokens[gt * 4 + 2];
        float phi = tokens[gt * 4 + 3];
        eta = fminf(fmaxf(eta, -20.f), 20.f);
        float sp, cp;
        sincosf(phi, &sp, &cp);
        float4 P;
        P.x = E;
        P.y = Pt * cp;
        P.z = Pt * sp;
        P.w = Pt * sinhf(eta);
        g_P[gt] = P;
    }

    __shared__ int red[256];
    red[threadIdx.x] = cnt;
    __syncthreads();
    for (int off = 128; off > 0; off >>= 1) {
        if (threadIdx.x < off) red[threadIdx.x] += red[threadIdx.x + off];
        __syncthreads();
    }
    if (threadIdx.x == 0) g_len[b] = red[0];
}

// =========================================================================
// Kernel 2: per-token top-8 Minkowski dot -> prefix-sum masses (k=2,4,8).
// One warp owns 32 consecutive tokens; s is broadcast from smem.
// Each lane keeps a private sorted (ascending) top-8 of (key, idx).
// =========================================================================
#define CSWAP(a, b, ia, ib) do {                         \
    bool _p = (a) > (b);                                 \
    float _t = _p ? (b) : (a);                           \
    (b) = _p ? (a) : (b);                                \
    (a) = _t;                                            \
    int _ti = _p ? (ib) : (ia);                          \
    (ib) = _p ? (ia) : (ib);                             \
    (ia) = _ti;                                          \
} while (0)

#define INSERT8(d, si) do {                              \
    k0 = (d); i0 = (si);                                 \
    CSWAP(k0, k1, i0, i1);                               \
    CSWAP(k1, k2, i1, i2);                               \
    CSWAP(k2, k3, i2, i3);                               \
    CSWAP(k3, k4, i3, i4);                               \
    CSWAP(k4, k5, i4, i5);                               \
    CSWAP(k5, k6, i5, i6);                               \
    CSWAP(k6, k7, i6, i7);                               \
} while (0)

__global__ __launch_bounds__(128) void mass_kernel()
{
    __shared__ __align__(16) float4 sP[T_];

    int b = blockIdx.y;
    int len = g_len[b];
    const float4* gp = g_P + b * T_;
    for (int i = threadIdx.x; i < T_; i += 128) sP[i] = gp[i];
    __syncthreads();

    int lane = threadIdx.x & 31;
    int t = blockIdx.x * 128 + (threadIdx.x >> 5) * 32 + lane;
    int gt = b * T_ + t;

    if (t >= len) {
        // masked token: m2 is zeroed by maskf -> mass = sqrt(1e-8)
        float mv = sqrtf(1e-8f);
        g_mass[gt * 3 + 0] = mv;
        g_mass[gt * 3 + 1] = mv;
        g_mass[gt * 3 + 2] = mv;
        return;
    }

    float4 pt = sP[t];
    float aE = pt.x, ax = -pt.y, ay = -pt.z, az = -pt.w;  // metric folded

    float k0 = -FLT_MAX, k1 = -FLT_MAX, k2 = -FLT_MAX, k3 = -FLT_MAX;
    float k4 = -FLT_MAX, k5 = -FLT_MAX, k6 = -FLT_MAX, k7 = -FLT_MAX;
    int i0 = 0, i1 = 0, i2 = 0, i3 = 0, i4 = 0, i5 = 0, i6 = 0, i7 = 0;

    int s = 0;
    int len4 = len & ~3;
    for (; s < len4; s += 4) {
        float4 p0 = sP[s + 0];
        float4 p1 = sP[s + 1];
        float4 p2 = sP[s + 2];
        float4 p3 = sP[s + 3];
        float d0 = fmaf(aE, p0.x, fmaf(ax, p0.y, fmaf(ay, p0.z, az * p0.w)));
        float d1 = fmaf(aE, p1.x, fmaf(ax, p1.y, fmaf(ay, p1.z, az * p1.w)));
        float d2 = fmaf(aE, p2.x, fmaf(ax, p2.y, fmaf(ay, p2.z, az * p2.w)));
        float d3 = fmaf(aE, p3.x, fmaf(ax, p3.y, fmaf(ay, p3.z, az * p3.w)));
        if (d0 > k0) INSERT8(d0, s + 0);
        if (d1 > k0) INSERT8(d1, s + 1);
        if (d2 > k0) INSERT8(d2, s + 2);
        if (d3 > k0) INSERT8(d3, s + 3);
    }
    for (; s < len; s++) {
        float4 p0 = sP[s];
        float d0 = fmaf(aE, p0.x, fmaf(ax, p0.y, fmaf(ay, p0.z, az * p0.w)));
        if (d0 > k0) INSERT8(d0, s);
    }

    // sequential cumsum in descending-value order (k7 is the max), matching ref
    float4 e7 = sP[i7], e6 = sP[i6], e5 = sP[i5], e4 = sP[i4];
    float4 e3 = sP[i3], e2 = sP[i2], e1 = sP[i1], e0 = sP[i0];

    float sx = e7.x + e6.x;
    float sy = e7.y + e6.y;
    float sz = e7.z + e6.z;
    float sw = e7.w + e6.w;
    float m2 = fmaf(sx, sx, -fmaf(sy, sy, fmaf(sz, sz, sw * sw)));
    g_mass[gt * 3 + 0] = sqrtf(fmaxf(m2, 0.f) + 1e-8f);

    sx += e5.x; sy += e5.y; sz += e5.z; sw += e5.w;
    sx += e4.x; sy += e4.y; sz += e4.z; sw += e4.w;
    m2 = fmaf(sx, sx, -fmaf(sy, sy, fmaf(sz, sz, sw * sw)));
    g_mass[gt * 3 + 1] = sqrtf(fmaxf(m2, 0.f) + 1e-8f);

    sx += e3.x; sy += e3.y; sz += e3.z; sw += e3.w;
    sx += e2.x; sy += e2.y; sz += e2.z; sw += e2.w;
    sx += e1.x; sy += e1.y; sz += e1.z; sw += e1.w;
    sx += e0.x; sy += e0.y; sz += e0.z; sw += e0.w;
    m2 = fmaf(sx, sx, -fmaf(sy, sy, fmaf(sz, sz, sw * sw)));
    g_mass[gt * 3 + 2] = sqrtf(fmaxf(m2, 0.f) + 1e-8f);
}

// =========================================================================
// Kernel 3: MLP  out = gelu(mass@W1 + b1) @ W2 + b2   (fp32, FFMA2-packed)
// Block: 64 tokens x 512 cols (4 chunks of 128). 128 threads, 8x8 tile.
// =========================================================================
__device__ __forceinline__ unsigned long long dup2(float a) {
    unsigned long long r;
    asm("mov.b64 %0, {%1, %1};" : "=l"(r) : "f"(a));
    return r;
}
__device__ __forceinline__ unsigned long long pack2(float lo, float hi) {
    unsigned long long r;
    asm("mov.b64 %0, {%1, %2};" : "=l"(r) : "f"(lo), "f"(hi));
    return r;
}
__device__ __forceinline__ float2 unpack2(unsigned long long v) {
    float2 f;
    asm("mov.b64 {%0, %1}, %2;" : "=f"(f.x), "=f"(f.y) : "l"(v));
    return f;
}
__device__ __forceinline__ unsigned long long fma2(
    unsigned long long a, unsigned long long b, unsigned long long c) {
    unsigned long long d;
    asm("fma.rn.f32x2 %0, %1, %2, %3;" : "=l"(d) : "l"(a), "l"(b), "l"(c));
    return d;
}

__global__ __launch_bounds__(128) void mlp_kernel(
    const float* __restrict__ W1, const float* __restrict__ b1,
    const float* __restrict__ W2, const float* __restrict__ b2,
    float* __restrict__ out)
{
    __shared__ __align__(16) float sA[H_][64];    // h transposed: [hidden][token]
    __shared__ __align__(16) float sB[H_][128];   // W2 chunk

    int tok0 = blockIdx.x * 64;
    int tid = threadIdx.x;

    // --- compute h (gelu exact) into sA ---
    {
        int t = tid & 63;
        int gt = tok0 + t;
        float m0 = g_mass[gt * 3 + 0];
        float m1 = g_mass[gt * 3 + 1];
        float m2v = g_mass[gt * 3 + 2];
        for (int j = (tid >> 6); j < H_; j += 2) {
            float x = fmaf(m0, W1[j], fmaf(m1, W1[H_ + j], fmaf(m2v, W1[2 * H_ + j], b1[j])));
            float h = 0.5f * x * (1.f + erff(x * 0.70710678118654752f));
            sA[j][t] = h;
        }
    }

    int tc = tid & 15;   // column group (8 cols each)
    int tr = tid >> 4;   // token group (8 tokens each)

    for (int nc = 0; nc < 4; nc++) {
        __syncthreads();   // protect sA (first iter) / sB reuse (later iters)
        // load W2 chunk [64][128]
        for (int i = tid; i < (H_ * 128) / 4; i += 128) {
            int k = i >> 5;
            int c4 = i & 31;
            ((float4*)(&sB[k][0]))[c4] =
                ((const float4*)(W2 + k * D_ + nc * 128))[c4];
        }
        __syncthreads();

        unsigned long long acc[8][4];
        {
            const float4 bb0 = *(const float4*)(b2 + nc * 128 + tc * 8);
            const float4 bb1 = *(const float4*)(b2 + nc * 128 + tc * 8 + 4);
            unsigned long long c0 = pack2(bb0.x, bb0.y);
            unsigned long long c1 = pack2(bb0.z, bb0.w);
            unsigned long long c2 = pack2(bb1.x, bb1.y);
            unsigned long long c3 = pack2(bb1.z, bb1.w);
#pragma unroll
            for (int ti = 0; ti < 8; ti++) {
                acc[ti][0] = c0; acc[ti][1] = c1; acc[ti][2] = c2; acc[ti][3] = c3;
            }
        }

#pragma unroll 8
        for (int k = 0; k < H_; k++) {
            float4 a0 = *(const float4*)&sA[k][tr * 8];
            float4 a1 = *(const float4*)&sA[k][tr * 8 + 4];
            ulonglong2 bv0 = *(const ulonglong2*)&sB[k][tc * 8];
            ulonglong2 bv1 = *(const ulonglong2*)&sB[k][tc * 8 + 4];
            float av[8] = {a0.x, a0.y, a0.z, a0.w, a1.x, a1.y, a1.z, a1.w};
#pragma unroll
            for (int ti = 0; ti < 8; ti++) {
                unsigned long long ad = dup2(av[ti]);
                acc[ti][0] = fma2(ad, bv0.x, acc[ti][0]);
                acc[ti][1] = fma2(ad, bv0.y, acc[ti][1]);
                acc[ti][2] = fma2(ad, bv1.x, acc[ti][2]);
                acc[ti][3] = fma2(ad, bv1.y, acc[ti][3]);
            }
        }

#pragma unroll
        for (int ti = 0; ti < 8; ti++) {
            float2 f0 = unpack2(acc[ti][0]);
            float2 f1 = unpack2(acc[ti][1]);
            float2 f2 = unpack2(acc[ti][2]);
            float2 f3 = unpack2(acc[ti][3]);
            float4 o0 = make_float4(f0.x, f0.y, f1.x, f1.y);
            float4 o1 = make_float4(f2.x, f2.y, f3.x, f3.y);
            float* op = out + (size_t)(tok0 + tr * 8 + ti) * D_ + nc * 128 + tc * 8;
            *(float4*)op = o0;
            *((float4*)op + 1) = o1;
        }
    }
}

// =========================================================================
extern "C" void kernel_launch(void* const* d_in, const int* in_sizes, int n_in,
                              void* d_out, int out_size)
{
    const float* tokens        = (const float*)d_in[0];
    const unsigned char* mask  = (const unsigned char*)d_in[1];
    const float* W1            = (const float*)d_in[2];
    const float* b1            = (const float*)d_in[3];
    const float* W2            = (const float*)d_in[4];
    const float* b2            = (const float*)d_in[5];
    float* out                 = (float*)d_out;

    prep_kernel<<<B_, 256>>>(tokens, mask);
    mass_kernel<<<dim3(T_ / 128, B_), 128>>>();
    mlp_kernel<<<(B_ * T_) / 64, 128>>>(W1, b1, W2, b2, out);
}